// round 2
// baseline (speedup 1.0000x reference)
#include <cuda_runtime.h>
#include <cstdint>

#define BATCH 64
#define S_LEN 2048
#define HID   256

// ---------------------------------------------------------------------------
// f32x2 packed-math helpers
// ---------------------------------------------------------------------------
__device__ __forceinline__ unsigned long long fma2(unsigned long long a,
                                                   unsigned long long b,
                                                   unsigned long long c) {
    unsigned long long d;
    asm("fma.rn.f32x2 %0, %1, %2, %3;" : "=l"(d) : "l"(a), "l"(b), "l"(c));
    return d;
}
__device__ __forceinline__ unsigned long long add2(unsigned long long a,
                                                   unsigned long long b) {
    unsigned long long d;
    asm("add.rn.f32x2 %0, %1, %2;" : "=l"(d) : "l"(a), "l"(b));
    return d;
}
__device__ __forceinline__ unsigned long long pack2(float x, float y) {
    unsigned long long r;
    asm("mov.b64 %0, {%1, %2};" : "=l"(r) : "f"(x), "f"(y));
    return r;
}
__device__ __forceinline__ float2 unpack2(unsigned long long v) {
    float2 r;
    asm("mov.b64 {%0, %1}, %2;" : "=f"(r.x), "=f"(r.y) : "l"(v));
    return r;
}

__device__ __forceinline__ unsigned smem_u32(const void* p) {
    return (unsigned)__cvta_generic_to_shared(p);
}
__device__ __forceinline__ unsigned mapa_peer(unsigned addr, unsigned rank) {
    unsigned r;
    asm("mapa.shared::cluster.u32 %0, %1, %2;" : "=r"(r) : "r"(addr), "r"(rank));
    return r;
}
__device__ __forceinline__ void st_cluster_f32(unsigned addr, float v) {
    asm volatile("st.shared::cluster.f32 [%0], %1;" :: "r"(addr), "f"(v) : "memory");
}
__device__ __forceinline__ void mbar_arrive_peer(unsigned addr) {
    asm volatile("mbarrier.arrive.release.cluster.shared::cluster.b64 _, [%0];"
                 :: "r"(addr) : "memory");
}
__device__ __forceinline__ void mbar_init(unsigned addr, unsigned count) {
    asm volatile("mbarrier.init.shared.b64 [%0], %1;" :: "r"(addr), "r"(count) : "memory");
}
__device__ __forceinline__ void mbar_wait_parity(unsigned addr, unsigned phase) {
    asm volatile(
        "{\n\t"
        ".reg .pred P;\n\t"
        "WL%=:\n\t"
        "mbarrier.try_wait.parity.acquire.cluster.shared::cta.b64 P, [%0], %1, 0x989680;\n\t"
        "@P bra WD%=;\n\t"
        "bra WL%=;\n\t"
        "WD%=:\n\t"
        "}" :: "r"(addr), "r"(phase) : "memory");
}
__device__ __forceinline__ void cluster_sync_all() {
    asm volatile("barrier.cluster.arrive.aligned;" ::: "memory");
    asm volatile("barrier.cluster.wait.aligned;" ::: "memory");
}

// ---------------------------------------------------------------------------
// Kernel 1: xW = X @ W_ih^T   (131072x256 @ 256x256) fp32, written into d_out
// (unchanged from round 1 — ~fp32 roofline bound)
// ---------------------------------------------------------------------------
__global__ void __launch_bounds__(256) xw_gemm(const float* __restrict__ X,
                                               const float* __restrict__ Wih,
                                               float* __restrict__ out) {
    __shared__ alignas(16) float Xs[32][68];
    __shared__ alignas(16) float Ws[32][68];

    const int tid = threadIdx.x;
    const int m0  = blockIdx.x * 64;
    const int h0  = blockIdx.y * 64;
    const int row = tid >> 2;
    const int c4  = tid & 3;
    const int tx  = tid & 15;
    const int ty  = tid >> 4;

    unsigned long long acc[4][2];
#pragma unroll
    for (int i = 0; i < 4; i++) { acc[i][0] = 0ull; acc[i][1] = 0ull; }

    const float* Xbase = X   + (size_t)(m0 + row) * 256;
    const float* Wbase = Wih + (size_t)(h0 + row) * 256;

    float4 xa = *(const float4*)(Xbase + 0  + c4 * 4);
    float4 xb = *(const float4*)(Xbase + 16 + c4 * 4);
    float4 wa = *(const float4*)(Wbase + 0  + c4 * 4);
    float4 wb = *(const float4*)(Wbase + 16 + c4 * 4);

#pragma unroll 1
    for (int k0 = 0; k0 < 256; k0 += 32) {
        __syncthreads();
#pragma unroll
        for (int e = 0; e < 4; e++) {
            Xs[c4 * 4 + e][row]      = (&xa.x)[e];
            Xs[16 + c4 * 4 + e][row] = (&xb.x)[e];
            Ws[c4 * 4 + e][row]      = (&wa.x)[e];
            Ws[16 + c4 * 4 + e][row] = (&wb.x)[e];
        }
        float4 nxa = make_float4(0, 0, 0, 0), nxb = nxa, nwa = nxa, nwb = nxa;
        if (k0 < 224) {
            nxa = *(const float4*)(Xbase + k0 + 32 + c4 * 4);
            nxb = *(const float4*)(Xbase + k0 + 48 + c4 * 4);
            nwa = *(const float4*)(Wbase + k0 + 32 + c4 * 4);
            nwb = *(const float4*)(Wbase + k0 + 48 + c4 * 4);
        }
        __syncthreads();

#pragma unroll
        for (int kk = 0; kk < 32; kk++) {
            float4 a4 = *(const float4*)(&Xs[kk][ty * 4]);
            const unsigned long long* bp =
                (const unsigned long long*)(&Ws[kk][tx * 4]);
            unsigned long long b0 = bp[0];
            unsigned long long b1 = bp[1];
            unsigned long long aa;
            aa = pack2(a4.x, a4.x);
            acc[0][0] = fma2(aa, b0, acc[0][0]); acc[0][1] = fma2(aa, b1, acc[0][1]);
            aa = pack2(a4.y, a4.y);
            acc[1][0] = fma2(aa, b0, acc[1][0]); acc[1][1] = fma2(aa, b1, acc[1][1]);
            aa = pack2(a4.z, a4.z);
            acc[2][0] = fma2(aa, b0, acc[2][0]); acc[2][1] = fma2(aa, b1, acc[2][1]);
            aa = pack2(a4.w, a4.w);
            acc[3][0] = fma2(aa, b0, acc[3][0]); acc[3][1] = fma2(aa, b1, acc[3][1]);
        }
        xa = nxa; xb = nxb; wa = nwa; wb = nwb;
    }

#pragma unroll
    for (int i = 0; i < 4; i++) {
        float2 p = unpack2(acc[i][0]);
        float2 q = unpack2(acc[i][1]);
        float4 v = make_float4(p.x, p.y, q.x, q.y);
        *(float4*)(out + (size_t)(m0 + ty * 4 + i) * 256 + h0 + tx * 4) = v;
    }
}

// ---------------------------------------------------------------------------
// Kernel 2 (v2): recurrence, 2-CTA cluster per batch.
// CTA rank r owns OUTPUTS [r*128, r*128+128). Thread pair (t, t+128) shares
// output o = r*128 + (t&127); the thread with khalf==rank ("early") covers
// k in own-output range and reads CTA-local h; the thread with khalf==peer
// ("late") covers the peer k-range and waits on the peer's h broadcast, whose
// DSMEM latency overlaps the early threads' FMA window. Pair partials combine
// through CTA-local smem; only final tanh'd h crosses CTAs (double-buffered,
// warp-elected mbarrier arrives).
// ---------------------------------------------------------------------------
__global__ void __launch_bounds__(256, 1) __cluster_dims__(2, 1, 1)
rnn_scan(const float* __restrict__ Whh, float* __restrict__ io,
         float* __restrict__ hn) {
    __shared__ alignas(16) float h_own[2][128];   // this CTA's outputs
    __shared__ alignas(16) float h_peer[2][128];  // peer outputs (DSMEM target)
    __shared__ alignas(16) float part[128];       // early partials
    __shared__ alignas(8)  unsigned long long mbar[2];

    unsigned rank;
    asm("mov.u32 %0, %%cluster_ctarank;" : "=r"(rank));
    const unsigned peer = rank ^ 1u;
    const int t = threadIdx.x;
    const int b = blockIdx.x >> 1;
    const int out_local = t & 127;
    const int khalf = t >> 7;                 // k in [khalf*128, +128)
    const bool early = ((unsigned)khalf == rank);
    const int o = (int)rank * 128 + out_local;  // output index this pair owns

    // W rows in registers: W[o][k], k in this thread's half. 64 fma2 regs.
    unsigned long long w[64];
    {
        const float4* wrow = (const float4*)(Whh + (size_t)o * 256 + khalf * 128);
#pragma unroll
        for (int i = 0; i < 32; i++) {
            float4 v = wrow[i];
            w[2 * i]     = pack2(v.x, v.y);
            w[2 * i + 1] = pack2(v.z, v.w);
        }
    }

    if (t < 128) { h_own[0][t] = 0.0f; h_peer[0][t] = 0.0f; }
    if (t == 0) {
        mbar_init(smem_u32(&mbar[0]), 4);   // 4 arrives: peer's 4 late warps
        mbar_init(smem_u32(&mbar[1]), 4);
        asm volatile("fence.mbarrier_init.release.cluster;" ::: "memory");
    }
    __syncthreads();
    cluster_sync_all();

    // Peer-side addresses (push final h into peer's h_peer + arrive peer mbar)
    const unsigned bar_peer[2] = {
        mapa_peer(smem_u32(&mbar[0]), peer),
        mapa_peer(smem_u32(&mbar[1]), peer)
    };
    const unsigned hpush_peer[2] = {
        mapa_peer(smem_u32(&h_peer[0][out_local]), peer),
        mapa_peer(smem_u32(&h_peer[1][out_local]), peer)
    };

    const float* hsrc = early ? &h_own[0][0] : &h_peer[0][0];
    float* xrow = io + (size_t)b * S_LEN * HID + o;  // column o, stride HID
    float xw_cur = early ? 0.0f : xrow[0];
    int ph0 = 0, ph1 = 0;

    for (int s = 0; s < S_LEN; s++) {
        const int buf = s & 1;

        float xw_nxt = 0.0f;
        if (!early) {
            if (s < S_LEN - 1) xw_nxt = xrow[(size_t)(s + 1) * HID]; // prefetch
            if (s > 0) {  // wait for peer h broadcast (overlaps early FMA)
                if (buf == 0) { mbar_wait_parity(smem_u32(&mbar[0]), ph0); ph0 ^= 1; }
                else          { mbar_wait_parity(smem_u32(&mbar[1]), ph1); ph1 ^= 1; }
            }
        }

        // 128-wide dot: 64 fma2, 4 accumulator chains (16 deep each)
        const ulonglong2* h2 = (const ulonglong2*)(hsrc + buf * 128);
        unsigned long long a0 = 0ull, a1 = 0ull, a2 = 0ull, a3 = 0ull;
#pragma unroll
        for (int j = 0; j < 16; j++) {
            ulonglong2 v0 = h2[2 * j];      // broadcast LDS.128
            ulonglong2 v1 = h2[2 * j + 1];
            a0 = fma2(w[4 * j],     v0.x, a0);
            a1 = fma2(w[4 * j + 1], v0.y, a1);
            a2 = fma2(w[4 * j + 2], v1.x, a2);
            a3 = fma2(w[4 * j + 3], v1.y, a3);
        }
        a0 = add2(a0, a1);
        a2 = add2(a2, a3);
        a0 = add2(a0, a2);
        float2 p = unpack2(a0);
        float partial = p.x + p.y;

        if (early) part[out_local] = partial;
        __syncthreads();  // SYNC1: part[] ready for late threads

        if (!early) {
            float v = tanhf(partial + part[out_local] + xw_cur);
            const int nbuf = (s + 1) & 1;
            h_own[nbuf][out_local] = v;            // own half for next step
            st_cluster_f32(hpush_peer[nbuf], v);   // broadcast to peer
            __syncwarp();
            if ((t & 31) == 0) mbar_arrive_peer(bar_peer[nbuf]);
            xrow[(size_t)s * HID] = v;             // output[b][s][o] in place
            if (s == S_LEN - 1) hn[(size_t)b * HID + o] = v;
            xw_cur = xw_nxt;
        }
        __syncthreads();  // SYNC2: h_own[nbuf] visible before next-step reads
    }

    cluster_sync_all();  // peer DSMEM traffic drained before exit
}

// ---------------------------------------------------------------------------
extern "C" void kernel_launch(void* const* d_in, const int* in_sizes, int n_in,
                              void* d_out, int out_size) {
    (void)in_sizes; (void)n_in; (void)out_size;
    const float* x   = (const float*)d_in[0];  // [64, 2048, 256]
    const float* wih = (const float*)d_in[1];  // [256, 256]
    const float* whh = (const float*)d_in[2];  // [256, 256]
    float* out = (float*)d_out;                           // output [64,2048,256]
    float* hn  = out + (size_t)BATCH * S_LEN * HID;       // h_n [1,64,256]

    dim3 grid_gemm(BATCH * S_LEN / 64, HID / 64);
    xw_gemm<<<grid_gemm, 256>>>(x, wih, out);

    rnn_scan<<<BATCH * 2, 256>>>(whh, out, hn);
}